// round 10
// baseline (speedup 1.0000x reference)
#include <cuda_runtime.h>
#include <stdint.h>

#define N_BITS 16

// Word-domain bitwise ripple-carry adder at the HBM roofline.
// Inputs are exactly {0x00000000, 0x3F800000}; the domain is closed under
// XOR/AND/OR so the reference's soft gates are exact LOP3 on raw words.
//
// One thread = one float4 = 4 bits of one row (lane-contiguous, minimal L1
// wavefronts). Group carry-in from 5 independent shuffles + flat LOP3 tree.
//
// Round-10 probe: stores use st.global.wt (write-through) instead of .cs --
// the last untested cache-policy knob. Writes are pure streaming (no reuse),
// so bypassing L2 write-back state may reduce R/W turnaround at the LTS.
__device__ __forceinline__ void stg128_wt(uint4* p, uint4 v) {
    asm volatile("st.global.wt.v4.b32 [%0], {%1,%2,%3,%4};"
                 :: "l"(p), "r"(v.x), "r"(v.y), "r"(v.z), "r"(v.w)
                 : "memory");
}

__global__ void __launch_bounds__(512)
ripple_cla_wt_kernel(const uint4* __restrict__ x4,
                     const uint4* __restrict__ y4,
                     uint4* __restrict__ s4,
                     uint4* __restrict__ c4)
{
    const int gid = blockIdx.x * blockDim.x + threadIdx.x;

    const uint4 xv = __ldcs(x4 + gid);
    const uint4 yv = __ldcs(y4 + gid);

    // Per-bit propagate / generate (word domain).
    const unsigned p0 = xv.x ^ yv.x, g0 = xv.x & yv.x;
    const unsigned p1 = xv.y ^ yv.y, g1 = xv.y & yv.y;
    const unsigned p2 = xv.z ^ yv.z, g2 = xv.z & yv.z;
    const unsigned p3 = xv.w ^ yv.w, g3 = xv.w & yv.w;

    // 4-bit group generate / propagate.
    const unsigned G = g3 | (p3 & (g2 | (p2 & (g1 | (p1 & g0)))));
    const unsigned P = p0 & p1 & p2 & p3;

    // Independent shuffles: G from lanes -1,-2,-3 and P from lanes -1,-2.
    const unsigned Gd1 = __shfl_up_sync(0xffffffffu, G, 1);
    const unsigned Gd2 = __shfl_up_sync(0xffffffffu, G, 2);
    const unsigned Gd3 = __shfl_up_sync(0xffffffffu, G, 3);
    const unsigned Pd1 = __shfl_up_sync(0xffffffffu, P, 1);
    const unsigned Pd2 = __shfl_up_sync(0xffffffffu, P, 2);

    // Segment position (4 lanes = 1 row); masks select valid terms.
    const unsigned seg = threadIdx.x & 3;
    const unsigned m1 = (unsigned)-(int)(seg >= 1);
    const unsigned m2 = (unsigned)-(int)(seg >= 2);
    const unsigned m3 = (unsigned)-(int)(seg >= 3);

    // Exclusive carry-in for this 4-bit group (flat LOP3 tree).
    const unsigned cin = m1 & (Gd1 | (Pd1 & (m2 & (Gd2 | (Pd2 & (m3 & Gd3))))));

    // Local 4-bit ripple with the group carry-in.
    const unsigned c0 = g0 | (p0 & cin);
    const unsigned c1 = g1 | (p1 & c0);
    const unsigned c2 = g2 | (p2 & c1);
    const unsigned c3 = g3 | (p3 & c2);

    uint4 sv;
    sv.x = p0 ^ cin; sv.y = p1 ^ c0; sv.z = p2 ^ c1; sv.w = p3 ^ c2;
    stg128_wt(s4 + gid, sv);

    uint4 cv;
    cv.x = c0; cv.y = c1; cv.z = c2; cv.w = c3;
    stg128_wt(c4 + gid, cv);
}

extern "C" void kernel_launch(void* const* d_in, const int* in_sizes, int n_in,
                              void* d_out, int out_size)
{
    const uint4* x4 = (const uint4*)d_in[0];
    const uint4* y4 = (const uint4*)d_in[1];
    const int n_elems = in_sizes[0];               // BATCH * 16 floats
    const int n4 = n_elems / 4;                    // 8388608 float4s

    unsigned* out = (unsigned*)d_out;
    uint4* s4 = (uint4*)out;                       // sum:   first half
    uint4* c4 = (uint4*)(out + (size_t)n_elems);   // carry: second half

    const int threads = 512;
    const int blocks = n4 / threads;               // 16384, divides exactly
    ripple_cla_wt_kernel<<<blocks, threads>>>(x4, y4, s4, c4);
}

// round 11
// speedup vs baseline: 1.0075x; 1.0075x over previous
#include <cuda_runtime.h>
#include <stdint.h>

#define N_BITS 16

// FINAL (= Round-7 measured best: bench 80.38us, ncu 74.88us, rel_err 0.0).
//
// Word-domain bitwise ripple-carry adder at the HBM roofline. Inputs are
// exactly {0x00000000, 0x3F800000}; that 2-value domain is closed under
// XOR/AND/OR, so the reference's differentiable soft gates are implemented
// EXACTLY by LOP3 on the raw 32-bit words (bit-identical, rel_err = 0).
//
// One thread = one float4 = 4 bits of one row -> every LDG.128/STG.128 is
// lane-contiguous (minimum L1 wavefronts; fixing this took 99us -> 80us).
// Carry chain: per-thread 4-bit (G,P) group; group carry-in from 5
// INDEPENDENT back-to-back shuffles + flat LOP3 tree; local 4-bit ripple.
// Loads .cs (evict-first), stores .cs (write-back streaming; .wt measured
// 1.3us slower in R10).
//
// Convergence evidence: six structural variants (ITEMS=2, persistent grid,
// dependent scan, flat scan, block 256/512, 256-bit v8.b32 ops) all measure
// ncu 74.7-75.4us = 536.9MB / 74.8us = ~7.2 TB/s effective goodput (~90% of
// 8 TB/s spec) with issue <= 15%: the mixed read/write HBM ceiling. Traffic
// is irreducible, so this is the roofline.
__global__ void __launch_bounds__(512)
ripple_cla_flat_kernel(const uint4* __restrict__ x4,
                       const uint4* __restrict__ y4,
                       uint4* __restrict__ s4,
                       uint4* __restrict__ c4)
{
    const int gid = blockIdx.x * blockDim.x + threadIdx.x;

    const uint4 xv = __ldcs(x4 + gid);
    const uint4 yv = __ldcs(y4 + gid);

    // Per-bit propagate / generate (word domain).
    const unsigned p0 = xv.x ^ yv.x, g0 = xv.x & yv.x;
    const unsigned p1 = xv.y ^ yv.y, g1 = xv.y & yv.y;
    const unsigned p2 = xv.z ^ yv.z, g2 = xv.z & yv.z;
    const unsigned p3 = xv.w ^ yv.w, g3 = xv.w & yv.w;

    // 4-bit group generate / propagate.
    const unsigned G = g3 | (p3 & (g2 | (p2 & (g1 | (p1 & g0)))));
    const unsigned P = p0 & p1 & p2 & p3;

    // Independent shuffles: G from lanes -1,-2,-3 and P from lanes -1,-2.
    const unsigned Gd1 = __shfl_up_sync(0xffffffffu, G, 1);
    const unsigned Gd2 = __shfl_up_sync(0xffffffffu, G, 2);
    const unsigned Gd3 = __shfl_up_sync(0xffffffffu, G, 3);
    const unsigned Pd1 = __shfl_up_sync(0xffffffffu, P, 1);
    const unsigned Pd2 = __shfl_up_sync(0xffffffffu, P, 2);

    // Segment position (4 lanes = 1 row); masks select valid terms.
    const unsigned seg = threadIdx.x & 3;
    const unsigned m1 = (unsigned)-(int)(seg >= 1);
    const unsigned m2 = (unsigned)-(int)(seg >= 2);
    const unsigned m3 = (unsigned)-(int)(seg >= 3);

    // Exclusive carry-in for this 4-bit group (flat LOP3 tree).
    const unsigned cin = m1 & (Gd1 | (Pd1 & (m2 & (Gd2 | (Pd2 & (m3 & Gd3))))));

    // Local 4-bit ripple with the group carry-in.
    const unsigned c0 = g0 | (p0 & cin);
    const unsigned c1 = g1 | (p1 & c0);
    const unsigned c2 = g2 | (p2 & c1);
    const unsigned c3 = g3 | (p3 & c2);

    uint4 sv;
    sv.x = p0 ^ cin; sv.y = p1 ^ c0; sv.z = p2 ^ c1; sv.w = p3 ^ c2;
    __stcs(s4 + gid, sv);

    uint4 cv;
    cv.x = c0; cv.y = c1; cv.z = c2; cv.w = c3;
    __stcs(c4 + gid, cv);
}

extern "C" void kernel_launch(void* const* d_in, const int* in_sizes, int n_in,
                              void* d_out, int out_size)
{
    const uint4* x4 = (const uint4*)d_in[0];
    const uint4* y4 = (const uint4*)d_in[1];
    const int n_elems = in_sizes[0];               // BATCH * 16 floats
    const int n4 = n_elems / 4;                    // 8388608 float4s

    unsigned* out = (unsigned*)d_out;
    uint4* s4 = (uint4*)out;                       // sum:   first half
    uint4* c4 = (uint4*)(out + (size_t)n_elems);   // carry: second half

    const int threads = 512;
    const int blocks = n4 / threads;               // 16384, divides exactly
    ripple_cla_flat_kernel<<<blocks, threads>>>(x4, y4, s4, c4);
}

// round 12
// speedup vs baseline: 1.0219x; 1.0143x over previous
#include <cuda_runtime.h>
#include <stdint.h>

#define N_BITS 16

// FINAL (= Round-7 measured best: bench 80.38us, ncu 74.88us, rel_err 0.0).
//
// Word-domain bitwise ripple-carry adder at the HBM roofline. Inputs are
// exactly {0x00000000, 0x3F800000}; that 2-value domain is closed under
// XOR/AND/OR, so the reference's differentiable soft gates are implemented
// EXACTLY by LOP3 on the raw 32-bit words (bit-identical, rel_err = 0).
//
// One thread = one float4 = 4 bits of one row -> every LDG.128/STG.128 is
// lane-contiguous (minimum L1 wavefronts; fixing this took 99us -> 80us).
// Carry chain: per-thread 4-bit (G,P) group; group carry-in from 5
// INDEPENDENT back-to-back shuffles + flat LOP3 tree; local 4-bit ripple.
// Loads/stores .cs (evict-first streaming; .wt measured 1.3us slower).
//
// Convergence evidence: seven structural variants (ITEMS=2, persistent grid,
// dependent scan, flat scan, block 256/512, 256-bit v8.b32 ops, .wt stores)
// all measure ncu 74.7-76.1us; the converged family sits at 536.9MB / 74.8us
// = ~7.2 TB/s effective goodput (~90% of 8 TB/s spec) with issue <= 15%:
// the mixed read/write HBM ceiling. Traffic is irreducible (dense fp32
// outputs mandated), so this is the roofline.
__global__ void __launch_bounds__(512)
ripple_cla_flat_kernel(const uint4* __restrict__ x4,
                       const uint4* __restrict__ y4,
                       uint4* __restrict__ s4,
                       uint4* __restrict__ c4)
{
    const int gid = blockIdx.x * blockDim.x + threadIdx.x;

    const uint4 xv = __ldcs(x4 + gid);
    const uint4 yv = __ldcs(y4 + gid);

    // Per-bit propagate / generate (word domain).
    const unsigned p0 = xv.x ^ yv.x, g0 = xv.x & yv.x;
    const unsigned p1 = xv.y ^ yv.y, g1 = xv.y & yv.y;
    const unsigned p2 = xv.z ^ yv.z, g2 = xv.z & yv.z;
    const unsigned p3 = xv.w ^ yv.w, g3 = xv.w & yv.w;

    // 4-bit group generate / propagate.
    const unsigned G = g3 | (p3 & (g2 | (p2 & (g1 | (p1 & g0)))));
    const unsigned P = p0 & p1 & p2 & p3;

    // Independent shuffles: G from lanes -1,-2,-3 and P from lanes -1,-2.
    const unsigned Gd1 = __shfl_up_sync(0xffffffffu, G, 1);
    const unsigned Gd2 = __shfl_up_sync(0xffffffffu, G, 2);
    const unsigned Gd3 = __shfl_up_sync(0xffffffffu, G, 3);
    const unsigned Pd1 = __shfl_up_sync(0xffffffffu, P, 1);
    const unsigned Pd2 = __shfl_up_sync(0xffffffffu, P, 2);

    // Segment position (4 lanes = 1 row); masks select valid terms.
    const unsigned seg = threadIdx.x & 3;
    const unsigned m1 = (unsigned)-(int)(seg >= 1);
    const unsigned m2 = (unsigned)-(int)(seg >= 2);
    const unsigned m3 = (unsigned)-(int)(seg >= 3);

    // Exclusive carry-in for this 4-bit group (flat LOP3 tree).
    const unsigned cin = m1 & (Gd1 | (Pd1 & (m2 & (Gd2 | (Pd2 & (m3 & Gd3))))));

    // Local 4-bit ripple with the group carry-in.
    const unsigned c0 = g0 | (p0 & cin);
    const unsigned c1 = g1 | (p1 & c0);
    const unsigned c2 = g2 | (p2 & c1);
    const unsigned c3 = g3 | (p3 & c2);

    uint4 sv;
    sv.x = p0 ^ cin; sv.y = p1 ^ c0; sv.z = p2 ^ c1; sv.w = p3 ^ c2;
    __stcs(s4 + gid, sv);

    uint4 cv;
    cv.x = c0; cv.y = c1; cv.z = c2; cv.w = c3;
    __stcs(c4 + gid, cv);
}

extern "C" void kernel_launch(void* const* d_in, const int* in_sizes, int n_in,
                              void* d_out, int out_size)
{
    const uint4* x4 = (const uint4*)d_in[0];
    const uint4* y4 = (const uint4*)d_in[1];
    const int n_elems = in_sizes[0];               // BATCH * 16 floats
    const int n4 = n_elems / 4;                    // 8388608 float4s

    unsigned* out = (unsigned*)d_out;
    uint4* s4 = (uint4*)out;                       // sum:   first half
    uint4* c4 = (uint4*)(out + (size_t)n_elems);   // carry: second half

    const int threads = 512;
    const int blocks = n4 / threads;               // 16384, divides exactly
    ripple_cla_flat_kernel<<<blocks, threads>>>(x4, y4, s4, c4);
}